// round 5
// baseline (speedup 1.0000x reference)
#include <cuda_runtime.h>
#include <cstdint>

#define BB 8
#define HH 64
#define WW 64
#define CC 512
#define NTOK (BB*HH*WW)        /* 32768 tokens */
#define E4D 2048
#define NHEADS 16
#define HD 32

// ---------------- GEMM tile config ------------------------------------------
// block tile: 128 rows x 256 cols; 16 warps (512 thr), warp tile 32x64
// k-chunk 32, 4-stage cp.async pipeline, one __syncthreads per chunk
#define KC 32
#define NSTG 4
#define AS_STRIDE 36           /* floats; conflict-free for frag reads */
#define BS_STRIDE 264          /* floats; 264 mod 32 == 8 -> conflict-free */
#define A_STAGE_F (128 * AS_STRIDE)            /* 4608 floats */
#define B_STAGE_F (32 * BS_STRIDE)             /* 8448 floats */
#define STAGE_F   (A_STAGE_F + B_STAGE_F)      /* 13056 floats = 52224 B */
#define SMEM_TOTAL (NSTG * STAGE_F * 4)        /* 208896 B */

// ---------------- scratch (device globals) ----------------------------------
__device__ float g_n1 [(size_t)NTOK * CC];
__device__ float g_qkv[(size_t)NTOK * 3 * CC];
__device__ float g_att[(size_t)NTOK * CC];
__device__ float g_msa[(size_t)NTOK * CC];
__device__ float g_act[(size_t)NTOK * E4D];

// ---------------- helpers ----------------------------------------------------
__device__ __forceinline__ uint32_t s2u(const void* p) {
    uint32_t a;
    asm("{ .reg .u64 t; cvta.to.shared.u64 t, %1; cvt.u32.u64 %0, t; }" : "=r"(a) : "l"(p));
    return a;
}
__device__ __forceinline__ void cpa16(uint32_t dst, const void* src) {
    asm volatile("cp.async.cg.shared.global [%0], [%1], 16;" :: "r"(dst), "l"(src));
}
#define CP_COMMIT() asm volatile("cp.async.commit_group;" ::: "memory")
#define CP_WAIT2()  asm volatile("cp.async.wait_group 2;" ::: "memory")

// ---------------- chunk loader (cp.async, 512 threads) -----------------------
__device__ __forceinline__ void load_chunk(uint32_t sb, int s, int ci, int tid,
                                           const float* __restrict__ A,
                                           const float* __restrict__ W,
                                           size_t rowBase, int colBase, int K, int M) {
    int kt = ci * KC;
    uint32_t abase = sb + (uint32_t)(s * STAGE_F * 4);
    uint32_t bbase = abase + A_STAGE_F * 4;
    // A tile: 128 rows x 32 floats (1024 float4, 2 per thread)
    #pragma unroll
    for (int i = 0; i < 2; i++) {
        int u = tid + i * 512;
        int r = u >> 3, w = u & 7;
        cpa16(abase + (uint32_t)(r * (AS_STRIDE * 4) + w * 16),
              A + (rowBase + r) * (size_t)K + kt + w * 4);
    }
    // B tile: 32 k-rows x 256 cols (2048 float4, 4 per thread)
    #pragma unroll
    for (int i = 0; i < 4; i++) {
        int u = tid + i * 512;
        int r = u >> 6, cq = u & 63;
        cpa16(bbase + (uint32_t)(r * (BS_STRIDE * 4) + cq * 16),
              W + (size_t)(kt + r) * M + colBase + cq * 4);
    }
    CP_COMMIT();
}

// ---------------- TF32 mma.sync GEMM ----------------------------------------
// out[N,M] = A[N,K] @ W[K,M] + epilogue. EPI: 0 bias, 1 bias+res, 2 bias+GELU
template<int EPI>
__global__ __launch_bounds__(512, 1)
void gemm_tf32(const float* __restrict__ A, const float* __restrict__ W,
               const float* __restrict__ bias, const float* __restrict__ res,
               float* __restrict__ out, int K, int M) {
    extern __shared__ __align__(16) float smem[];
    uint32_t sb = s2u(smem);
    int tid  = threadIdx.x;
    int lane = tid & 31;
    int warp = tid >> 5;
    int wm = warp & 3;               // 4 warps along rows (4*32 = 128)
    int wn = warp >> 2;              // 4 warps along cols (4*64 = 256)
    size_t rowBase = (size_t)blockIdx.y * 128;
    int    colBase = blockIdx.x * 256;
    int nchunk = K / KC;

    float c[2][8][4];
    #pragma unroll
    for (int i = 0; i < 2; i++)
        #pragma unroll
        for (int j = 0; j < 8; j++)
            #pragma unroll
            for (int k = 0; k < 4; k++) c[i][j][k] = 0.f;

    // prologue: 3 chunks in flight
    load_chunk(sb, 0, 0, tid, A, W, rowBase, colBase, K, M);
    load_chunk(sb, 1, 1, tid, A, W, rowBase, colBase, K, M);
    load_chunk(sb, 2, 2, tid, A, W, rowBase, colBase, K, M);

    for (int ci = 0; ci < nchunk; ci++) {
        int s = ci & (NSTG - 1);
        CP_WAIT2();
        __syncthreads();
        // issue next loads first (stage (ci+3)%4 != s; its last reader was
        // iteration ci-1, which every warp finished before this barrier)
        if (ci + 3 < nchunk)
            load_chunk(sb, (ci + 3) & (NSTG - 1), ci + 3, tid, A, W,
                       rowBase, colBase, K, M);

        const float* As = smem + s * STAGE_F;
        const float* Bs = As + A_STAGE_F;

        #pragma unroll
        for (int ks = 0; ks < 4; ks++) {
            int k0 = ks * 8;
            uint32_t a[2][4];
            #pragma unroll
            for (int mt = 0; mt < 2; mt++) {
                int r0 = wm * 32 + mt * 16 + (lane >> 2);
                int kc = k0 + (lane & 3);
                a[mt][0] = __float_as_uint(As[r0 * AS_STRIDE + kc]);
                a[mt][1] = __float_as_uint(As[(r0 + 8) * AS_STRIDE + kc]);
                a[mt][2] = __float_as_uint(As[r0 * AS_STRIDE + kc + 4]);
                a[mt][3] = __float_as_uint(As[(r0 + 8) * AS_STRIDE + kc + 4]);
            }
            #pragma unroll
            for (int nt = 0; nt < 8; nt++) {
                int col = wn * 64 + nt * 8 + (lane >> 2);
                uint32_t b0 = __float_as_uint(Bs[(k0 + (lane & 3)) * BS_STRIDE + col]);
                uint32_t b1 = __float_as_uint(Bs[(k0 + (lane & 3) + 4) * BS_STRIDE + col]);
                #pragma unroll
                for (int mt = 0; mt < 2; mt++) {
                    asm volatile(
                        "mma.sync.aligned.m16n8k8.row.col.f32.tf32.tf32.f32 "
                        "{%0,%1,%2,%3}, {%4,%5,%6,%7}, {%8,%9}, {%0,%1,%2,%3};"
                        : "+f"(c[mt][nt][0]), "+f"(c[mt][nt][1]),
                          "+f"(c[mt][nt][2]), "+f"(c[mt][nt][3])
                        : "r"(a[mt][0]), "r"(a[mt][1]), "r"(a[mt][2]), "r"(a[mt][3]),
                          "r"(b0), "r"(b1));
                }
            }
        }
    }

    // ---------------- epilogue ----------------
    #pragma unroll
    for (int mt = 0; mt < 2; mt++) {
        int r0 = wm * 32 + mt * 16 + (lane >> 2);
        #pragma unroll
        for (int nt = 0; nt < 8; nt++) {
            int col = colBase + wn * 64 + nt * 8 + 2 * (lane & 3);
            float2 bv = *(const float2*)(bias + col);
            #pragma unroll
            for (int half = 0; half < 2; half++) {
                size_t row = rowBase + r0 + half * 8;
                float v0 = c[mt][nt][half * 2 + 0] + bv.x;
                float v1 = c[mt][nt][half * 2 + 1] + bv.y;
                if (EPI == 1) {
                    float2 rv = *(const float2*)(res + row * (size_t)M + col);
                    v0 += rv.x; v1 += rv.y;
                }
                if (EPI == 2) {
                    v0 = 0.5f * v0 * (1.f + erff(v0 * 0.70710678118f));
                    v1 = 0.5f * v1 * (1.f + erff(v1 * 0.70710678118f));
                }
                float2 ov; ov.x = v0; ov.y = v1;
                *(float2*)(out + row * (size_t)M + col) = ov;
            }
        }
    }
}

// ---------------- LayerNorm --------------------------------------------------
__global__ void ln_kernel(const float* __restrict__ in,
                          const float* __restrict__ g,
                          const float* __restrict__ b,
                          float* __restrict__ out) {
    int row = blockIdx.x;
    int tid = threadIdx.x;
    const float2* xr = (const float2*)(in + (size_t)row * CC);
    float2 v = xr[tid];
    float s  = v.x + v.y;
    float sq = v.x * v.x + v.y * v.y;
    #pragma unroll
    for (int o = 16; o; o >>= 1) {
        s  += __shfl_xor_sync(0xffffffffu, s,  o);
        sq += __shfl_xor_sync(0xffffffffu, sq, o);
    }
    __shared__ float ss[8], sqq[8];
    int w = tid >> 5, l = tid & 31;
    if (!l) { ss[w] = s; sqq[w] = sq; }
    __syncthreads();
    s = 0.f; sq = 0.f;
    #pragma unroll
    for (int i = 0; i < 8; i++) { s += ss[i]; sq += sqq[i]; }
    float mean = s * (1.f / CC);
    float var  = sq * (1.f / CC) - mean * mean;
    float rstd = rsqrtf(var + 1e-5f);
    float2 gg = ((const float2*)g)[tid];
    float2 bb = ((const float2*)b)[tid];
    float2 o;
    o.x = (v.x - mean) * rstd * gg.x + bb.x;
    o.y = (v.y - mean) * rstd * gg.y + bb.y;
    ((float2*)(out + (size_t)row * CC))[tid] = o;
}

// ---------------- window attention -------------------------------------------
__global__ __launch_bounds__(64)
void attn_kernel(const float* __restrict__ qkv, float* __restrict__ out) {
    int blk  = blockIdx.x;
    int head = blk & (NHEADS - 1);
    int win  = blk >> 4;
    int b  = win >> 6;
    int wi = (win >> 3) & 7;
    int wj = win & 7;
    int p = threadIdx.x;
    int r = p >> 3, cc = p & 7;
    int t = b * (HH * WW) + (wi * 8 + r) * WW + wj * 8 + cc;

    __shared__ float Ks[64][33];
    __shared__ float Vs[64][33];

    const float4* base = (const float4*)(qkv + (size_t)t * (3 * CC) + head * 96);
    float q[HD];
    #pragma unroll
    for (int i = 0; i < 8; i++) {
        float4 vq = base[i];
        q[4*i+0] = vq.x; q[4*i+1] = vq.y; q[4*i+2] = vq.z; q[4*i+3] = vq.w;
        float4 vk = base[8 + i];
        Ks[p][4*i+0] = vk.x; Ks[p][4*i+1] = vk.y; Ks[p][4*i+2] = vk.z; Ks[p][4*i+3] = vk.w;
        float4 vv = base[16 + i];
        Vs[p][4*i+0] = vv.x; Vs[p][4*i+1] = vv.y; Vs[p][4*i+2] = vv.z; Vs[p][4*i+3] = vv.w;
    }
    __syncthreads();

    const float scale = 0.17677669529663688f;
    float s[64];
    float mx = -1e30f;
    #pragma unroll 4
    for (int j = 0; j < 64; j++) {
        float acc = 0.f;
        #pragma unroll
        for (int d = 0; d < HD; d++) acc += q[d] * Ks[j][d];
        acc *= scale;
        s[j] = acc;
        mx = fmaxf(mx, acc);
    }
    float sum = 0.f;
    #pragma unroll 4
    for (int j = 0; j < 64; j++) {
        float e = __expf(s[j] - mx);
        s[j] = e;
        sum += e;
    }
    float inv = 1.f / sum;

    float o[HD];
    #pragma unroll
    for (int d = 0; d < HD; d++) o[d] = 0.f;
    #pragma unroll 4
    for (int j = 0; j < 64; j++) {
        float pj = s[j] * inv;
        #pragma unroll
        for (int d = 0; d < HD; d++) o[d] += pj * Vs[j][d];
    }

    float4* op = (float4*)(out + (size_t)t * CC + head * HD);
    #pragma unroll
    for (int i = 0; i < 8; i++) {
        float4 v; v.x = o[4*i]; v.y = o[4*i+1]; v.z = o[4*i+2]; v.w = o[4*i+3];
        op[i] = v;
    }
}

// ---------------- launch -----------------------------------------------------
extern "C" void kernel_launch(void* const* d_in, const int* in_sizes, int n_in,
                              void* d_out, int out_size) {
    const float* x      = (const float*)d_in[0];
    const float* ln1_g  = (const float*)d_in[1];
    const float* ln1_b  = (const float*)d_in[2];
    const float* w_qkv  = (const float*)d_in[3];
    const float* b_qkv  = (const float*)d_in[4];
    const float* w_proj = (const float*)d_in[5];
    const float* b_proj = (const float*)d_in[6];
    const float* ln2_g  = (const float*)d_in[7];
    const float* ln2_b  = (const float*)d_in[8];
    const float* w1     = (const float*)d_in[9];
    const float* b1     = (const float*)d_in[10];
    const float* w2     = (const float*)d_in[11];
    const float* b2     = (const float*)d_in[12];
    float* out = (float*)d_out;

    float *n1, *qkv, *att, *msa, *act;
    cudaGetSymbolAddress((void**)&n1,  g_n1);
    cudaGetSymbolAddress((void**)&qkv, g_qkv);
    cudaGetSymbolAddress((void**)&att, g_att);
    cudaGetSymbolAddress((void**)&msa, g_msa);
    cudaGetSymbolAddress((void**)&act, g_act);

    cudaFuncSetAttribute(gemm_tf32<0>, cudaFuncAttributeMaxDynamicSharedMemorySize, SMEM_TOTAL);
    cudaFuncSetAttribute(gemm_tf32<1>, cudaFuncAttributeMaxDynamicSharedMemorySize, SMEM_TOTAL);
    cudaFuncSetAttribute(gemm_tf32<2>, cudaFuncAttributeMaxDynamicSharedMemorySize, SMEM_TOTAL);

    // 1) LN1 (shift dropped: SHIFT==WS so rolls cancel with window partition)
    ln_kernel<<<NTOK, 256>>>(x, ln1_g, ln1_b, n1);
    // 2) qkv = n1 @ w_qkv + b_qkv           [32768 x 1536]
    gemm_tf32<0><<<dim3(1536 / 256, NTOK / 128), 512, SMEM_TOTAL>>>(n1, w_qkv, b_qkv, nullptr, qkv, CC, 3 * CC);
    // 3) window attention (512 windows x 16 heads)
    attn_kernel<<<512 * NHEADS, 64>>>(qkv, att);
    // 4) msa = att @ w_proj + b_proj + x    [32768 x 512]
    gemm_tf32<1><<<dim3(CC / 256, NTOK / 128), 512, SMEM_TOTAL>>>(att, w_proj, b_proj, x, msa, CC, CC);
    // 5) LN2 (reuse n1 buffer)
    ln_kernel<<<NTOK, 256>>>(msa, ln2_g, ln2_b, n1);
    // 6) act = gelu(n1 @ w1 + b1)           [32768 x 2048]
    gemm_tf32<2><<<dim3(E4D / 256, NTOK / 128), 512, SMEM_TOTAL>>>(n1, w1, b1, nullptr, act, CC, E4D);
    // 7) out = act @ w2 + b2 + msa          [32768 x 512]
    gemm_tf32<1><<<dim3(CC / 256, NTOK / 128), 512, SMEM_TOTAL>>>(act, w2, b2, msa, out, E4D, CC);
}

// round 6
// speedup vs baseline: 1.7259x; 1.7259x over previous
#include <cuda_runtime.h>
#include <cuda_fp16.h>
#include <cstdint>

#define BB 8
#define HH 64
#define WW 64
#define CC 512
#define NTOK (BB*HH*WW)        /* 32768 tokens */
#define E4D 2048
#define NHEADS 16
#define HD 32

// ---------------- GEMM tile config ------------------------------------------
// block tile 128 x 256, KC=64, 16 warps (512 thr), warp tile 32x64
// fp16 mma.m16n8k16, ldmatrix feeds, 4-stage cp.async pipeline
#define KC 64
#define NSTG 4
#define A_BYTES 16384          /* 128 rows x 128B */
#define B_BYTES 32768          /* 64 rows x 512B */
#define STAGE_BYTES (A_BYTES + B_BYTES)        /* 49152 */
#define SMEM_TOTAL (NSTG * STAGE_BYTES)        /* 196608 */

// ---------------- scratch (device globals) ----------------------------------
__device__ __align__(16) __half g_n1h [(size_t)NTOK * CC];
__device__ __align__(16) __half g_qkvh[(size_t)NTOK * 3 * CC];
__device__ __align__(16) __half g_atth[(size_t)NTOK * CC];
__device__ __align__(16) __half g_acth[(size_t)NTOK * E4D];
__device__ float g_msa[(size_t)NTOK * CC];
__device__ __align__(16) __half g_wqkvh[(size_t)CC * 3 * CC];
__device__ __align__(16) __half g_wprojh[(size_t)CC * CC];
__device__ __align__(16) __half g_w1h[(size_t)CC * E4D];
__device__ __align__(16) __half g_w2h[(size_t)E4D * CC];

// ---------------- helpers ----------------------------------------------------
__device__ __forceinline__ uint32_t s2u(const void* p) {
    uint32_t a;
    asm("{ .reg .u64 t; cvta.to.shared.u64 t, %1; cvt.u32.u64 %0, t; }" : "=r"(a) : "l"(p));
    return a;
}
__device__ __forceinline__ void cpa16(uint32_t dst, const void* src) {
    asm volatile("cp.async.cg.shared.global [%0], [%1], 16;" :: "r"(dst), "l"(src));
}
#define CP_COMMIT() asm volatile("cp.async.commit_group;" ::: "memory")
#define CP_WAIT2()  asm volatile("cp.async.wait_group 2;" ::: "memory")

__device__ __forceinline__ void ldsm4(uint32_t* r, uint32_t addr) {
    asm volatile("ldmatrix.sync.aligned.m8n8.x4.shared.b16 {%0,%1,%2,%3}, [%4];"
        : "=r"(r[0]), "=r"(r[1]), "=r"(r[2]), "=r"(r[3]) : "r"(addr));
}
__device__ __forceinline__ void ldsm4t(uint32_t* r, uint32_t addr) {
    asm volatile("ldmatrix.sync.aligned.m8n8.x4.trans.shared.b16 {%0,%1,%2,%3}, [%4];"
        : "=r"(r[0]), "=r"(r[1]), "=r"(r[2]), "=r"(r[3]) : "r"(addr));
}
__device__ __forceinline__ void mma16816(float* c, const uint32_t* a, const uint32_t* b) {
    asm volatile(
        "mma.sync.aligned.m16n8k16.row.col.f32.f16.f16.f32 "
        "{%0,%1,%2,%3}, {%4,%5,%6,%7}, {%8,%9}, {%0,%1,%2,%3};"
        : "+f"(c[0]), "+f"(c[1]), "+f"(c[2]), "+f"(c[3])
        : "r"(a[0]), "r"(a[1]), "r"(a[2]), "r"(a[3]), "r"(b[0]), "r"(b[1]));
}

// ---------------- chunk loader (fp16, XOR-swizzled smem) ---------------------
__device__ __forceinline__ void load_chunk(uint32_t sb, int s, int ci, int tid,
                                           const __half* __restrict__ A,
                                           const __half* __restrict__ W,
                                           size_t rowBase, int colBase, int K, int M) {
    int kt = ci * KC;
    uint32_t Ab = sb + (uint32_t)(s * STAGE_BYTES);
    uint32_t Bb = Ab + A_BYTES;
    // A: 128 rows x 64 fp16 (128B rows, 8 granules, g ^= row&7)
    #pragma unroll
    for (int i = 0; i < 2; i++) {
        int u = tid + i * 512;
        int r = u >> 3, g = u & 7;
        cpa16(Ab + (uint32_t)(r * 128 + ((g ^ (r & 7)) << 4)),
              A + (rowBase + r) * (size_t)K + kt + g * 8);
    }
    // B: 64 k-rows x 256 fp16 (512B rows, 32 granules, low3(gn) ^= k&7)
    #pragma unroll
    for (int i = 0; i < 4; i++) {
        int u = tid + i * 512;
        int k = u >> 5, gn = u & 31;
        cpa16(Bb + (uint32_t)(k * 512 + ((gn ^ (k & 7)) << 4)),
              W + (size_t)(kt + k) * M + colBase + gn * 8);
    }
    CP_COMMIT();
}

// ---------------- fp16 mma GEMM ----------------------------------------------
// out[N,M] = A[N,K] @ W[K,M] + epilogue. EPI: 0 bias, 1 bias+res, 2 bias+GELU
// OUTH: write __half output (else float)
template<int EPI, bool OUTH>
__global__ __launch_bounds__(512, 1)
void gemm_h(const __half* __restrict__ A, const __half* __restrict__ W,
            const float* __restrict__ bias, const float* __restrict__ res,
            void* __restrict__ outp, int K, int M) {
    extern __shared__ __align__(16) char smem[];
    uint32_t sb = s2u(smem);
    int tid  = threadIdx.x;
    int lane = tid & 31;
    int warp = tid >> 5;
    int wm = warp & 3;               // 4 warps x 32 rows = 128
    int wn = warp >> 2;              // 4 warps x 64 cols = 256
    size_t rowBase = (size_t)blockIdx.y * 128;
    int    colBase = blockIdx.x * 256;
    int nchunk = K / KC;

    float c[2][8][4];
    #pragma unroll
    for (int i = 0; i < 2; i++)
        #pragma unroll
        for (int j = 0; j < 8; j++)
            #pragma unroll
            for (int k = 0; k < 4; k++) c[i][j][k] = 0.f;

    load_chunk(sb, 0, 0, tid, A, W, rowBase, colBase, K, M);
    load_chunk(sb, 1, 1, tid, A, W, rowBase, colBase, K, M);
    load_chunk(sb, 2, 2, tid, A, W, rowBase, colBase, K, M);

    for (int ci = 0; ci < nchunk; ci++) {
        int s = ci & (NSTG - 1);
        CP_WAIT2();
        __syncthreads();
        if (ci + 3 < nchunk)
            load_chunk(sb, (ci + 3) & (NSTG - 1), ci + 3, tid, A, W,
                       rowBase, colBase, K, M);
        else
            CP_COMMIT();   // empty group: keeps wait_group 2 <-> chunk ci invariant

        uint32_t Ab = sb + (uint32_t)(s * STAGE_BYTES);
        uint32_t Bb = Ab + A_BYTES;

        #pragma unroll
        for (int ks = 0; ks < 4; ks++) {
            uint32_t a[2][4];
            #pragma unroll
            for (int mt = 0; mt < 2; mt++) {
                int row = wm * 32 + mt * 16 + (lane & 15);
                int g = 2 * ks + (lane >> 4);
                ldsm4(a[mt], Ab + (uint32_t)(row * 128 + ((g ^ (row & 7)) << 4)));
            }
            uint32_t b[8][2];
            #pragma unroll
            for (int pr = 0; pr < 4; pr++) {
                int krow = ks * 16 + (lane & 7) + (((lane >> 3) & 1) << 3);
                int gn = wn * 8 + pr * 2 + (lane >> 4);
                uint32_t t[4];
                ldsm4t(t, Bb + (uint32_t)(krow * 512 + ((gn ^ (krow & 7)) << 4)));
                b[2*pr][0] = t[0]; b[2*pr][1] = t[1];
                b[2*pr+1][0] = t[2]; b[2*pr+1][1] = t[3];
            }
            #pragma unroll
            for (int mt = 0; mt < 2; mt++)
                #pragma unroll
                for (int nt = 0; nt < 8; nt++)
                    mma16816(c[mt][nt], a[mt], b[nt]);
        }
    }

    // ---------------- epilogue ----------------
    #pragma unroll
    for (int mt = 0; mt < 2; mt++) {
        int r0 = wm * 32 + mt * 16 + (lane >> 2);
        #pragma unroll
        for (int nt = 0; nt < 8; nt++) {
            int col = colBase + wn * 64 + nt * 8 + 2 * (lane & 3);
            float2 bv = *(const float2*)(bias + col);
            #pragma unroll
            for (int half = 0; half < 2; half++) {
                size_t row = rowBase + r0 + half * 8;
                float v0 = c[mt][nt][half * 2 + 0] + bv.x;
                float v1 = c[mt][nt][half * 2 + 1] + bv.y;
                if (EPI == 1) {
                    float2 rv = *(const float2*)(res + row * (size_t)M + col);
                    v0 += rv.x; v1 += rv.y;
                }
                if (EPI == 2) {
                    v0 = 0.5f * v0 * (1.f + erff(v0 * 0.70710678118f));
                    v1 = 0.5f * v1 * (1.f + erff(v1 * 0.70710678118f));
                }
                if (OUTH) {
                    *(__half2*)((__half*)outp + row * (size_t)M + col) =
                        __floats2half2_rn(v0, v1);
                } else {
                    float2 ov; ov.x = v0; ov.y = v1;
                    *(float2*)((float*)outp + row * (size_t)M + col) = ov;
                }
            }
        }
    }
}

// ---------------- fp32 -> fp16 convert ---------------------------------------
__global__ void f2h_kernel(const float* __restrict__ in, __half* __restrict__ out) {
    int idx = blockIdx.x * blockDim.x + threadIdx.x;   // 8 floats per thread
    const float4* i4 = (const float4*)in;
    float4 v0 = i4[2 * idx], v1 = i4[2 * idx + 1];
    __half2* o2 = (__half2*)out + 4 * idx;
    o2[0] = __floats2half2_rn(v0.x, v0.y);
    o2[1] = __floats2half2_rn(v0.z, v0.w);
    o2[2] = __floats2half2_rn(v1.x, v1.y);
    o2[3] = __floats2half2_rn(v1.z, v1.w);
}

// ---------------- LayerNorm (fp32 in, fp16 out) ------------------------------
__global__ void ln_kernel(const float* __restrict__ in,
                          const float* __restrict__ g,
                          const float* __restrict__ b,
                          __half* __restrict__ out) {
    int row = blockIdx.x;
    int tid = threadIdx.x;
    const float2* xr = (const float2*)(in + (size_t)row * CC);
    float2 v = xr[tid];
    float s  = v.x + v.y;
    float sq = v.x * v.x + v.y * v.y;
    #pragma unroll
    for (int o = 16; o; o >>= 1) {
        s  += __shfl_xor_sync(0xffffffffu, s,  o);
        sq += __shfl_xor_sync(0xffffffffu, sq, o);
    }
    __shared__ float ss[8], sqq[8];
    int w = tid >> 5, l = tid & 31;
    if (!l) { ss[w] = s; sqq[w] = sq; }
    __syncthreads();
    s = 0.f; sq = 0.f;
    #pragma unroll
    for (int i = 0; i < 8; i++) { s += ss[i]; sq += sqq[i]; }
    float mean = s * (1.f / CC);
    float var  = sq * (1.f / CC) - mean * mean;
    float rstd = rsqrtf(var + 1e-5f);
    float2 gg = ((const float2*)g)[tid];
    float2 bb = ((const float2*)b)[tid];
    float ox = (v.x - mean) * rstd * gg.x + bb.x;
    float oy = (v.y - mean) * rstd * gg.y + bb.y;
    ((__half2*)(out + (size_t)row * CC))[tid] = __floats2half2_rn(ox, oy);
}

// ---------------- window attention (fp16 in/out, fp32 math) ------------------
__device__ __forceinline__ void h8f(uint4 v, float* d) {
    __half2* h = (__half2*)&v;
    #pragma unroll
    for (int j = 0; j < 4; j++) {
        float2 f = __half22float2(h[j]);
        d[2*j] = f.x; d[2*j+1] = f.y;
    }
}

__global__ __launch_bounds__(64)
void attn_kernel(const __half* __restrict__ qkv, __half* __restrict__ out) {
    int blk  = blockIdx.x;
    int head = blk & (NHEADS - 1);
    int win  = blk >> 4;
    int b  = win >> 6;
    int wi = (win >> 3) & 7;
    int wj = win & 7;
    int p = threadIdx.x;
    int r = p >> 3, cc = p & 7;
    int t = b * (HH * WW) + (wi * 8 + r) * WW + wj * 8 + cc;

    __shared__ float Ks[64][33];
    __shared__ float Vs[64][33];

    const uint4* base = (const uint4*)(qkv + (size_t)t * (3 * CC) + head * 96);
    float q[HD];
    #pragma unroll
    for (int i = 0; i < 4; i++) {
        h8f(base[i], q + 8 * i);
        float tmp[8];
        h8f(base[4 + i], tmp);
        #pragma unroll
        for (int j = 0; j < 8; j++) Ks[p][8*i + j] = tmp[j];
        h8f(base[8 + i], tmp);
        #pragma unroll
        for (int j = 0; j < 8; j++) Vs[p][8*i + j] = tmp[j];
    }
    __syncthreads();

    const float scale = 0.17677669529663688f;
    float s[64];
    float mx = -1e30f;
    #pragma unroll 4
    for (int j = 0; j < 64; j++) {
        float acc = 0.f;
        #pragma unroll
        for (int d = 0; d < HD; d++) acc += q[d] * Ks[j][d];
        acc *= scale;
        s[j] = acc;
        mx = fmaxf(mx, acc);
    }
    float sum = 0.f;
    #pragma unroll 4
    for (int j = 0; j < 64; j++) {
        float e = __expf(s[j] - mx);
        s[j] = e;
        sum += e;
    }
    float inv = 1.f / sum;

    float o[HD];
    #pragma unroll
    for (int d = 0; d < HD; d++) o[d] = 0.f;
    #pragma unroll 4
    for (int j = 0; j < 64; j++) {
        float pj = s[j] * inv;
        #pragma unroll
        for (int d = 0; d < HD; d++) o[d] += pj * Vs[j][d];
    }

    __half2* op = (__half2*)(out + (size_t)t * CC + head * HD);
    #pragma unroll
    for (int i = 0; i < 16; i++)
        op[i] = __floats2half2_rn(o[2*i], o[2*i+1]);
}

// ---------------- launch -----------------------------------------------------
extern "C" void kernel_launch(void* const* d_in, const int* in_sizes, int n_in,
                              void* d_out, int out_size) {
    const float* x      = (const float*)d_in[0];
    const float* ln1_g  = (const float*)d_in[1];
    const float* ln1_b  = (const float*)d_in[2];
    const float* w_qkv  = (const float*)d_in[3];
    const float* b_qkv  = (const float*)d_in[4];
    const float* w_proj = (const float*)d_in[5];
    const float* b_proj = (const float*)d_in[6];
    const float* ln2_g  = (const float*)d_in[7];
    const float* ln2_b  = (const float*)d_in[8];
    const float* w1     = (const float*)d_in[9];
    const float* b1     = (const float*)d_in[10];
    const float* w2     = (const float*)d_in[11];
    const float* b2     = (const float*)d_in[12];
    float* out = (float*)d_out;

    __half *n1h, *qkvh, *atth, *acth, *wqkvh, *wprojh, *w1h, *w2h;
    float* msa;
    cudaGetSymbolAddress((void**)&n1h,   g_n1h);
    cudaGetSymbolAddress((void**)&qkvh,  g_qkvh);
    cudaGetSymbolAddress((void**)&atth,  g_atth);
    cudaGetSymbolAddress((void**)&acth,  g_acth);
    cudaGetSymbolAddress((void**)&msa,   g_msa);
    cudaGetSymbolAddress((void**)&wqkvh, g_wqkvh);
    cudaGetSymbolAddress((void**)&wprojh,g_wprojh);
    cudaGetSymbolAddress((void**)&w1h,   g_w1h);
    cudaGetSymbolAddress((void**)&w2h,   g_w2h);

    cudaFuncSetAttribute(gemm_h<0,true >, cudaFuncAttributeMaxDynamicSharedMemorySize, SMEM_TOTAL);
    cudaFuncSetAttribute(gemm_h<1,false>, cudaFuncAttributeMaxDynamicSharedMemorySize, SMEM_TOTAL);
    cudaFuncSetAttribute(gemm_h<2,true >, cudaFuncAttributeMaxDynamicSharedMemorySize, SMEM_TOTAL);

    // 0) weights -> fp16 (each thread handles 8 floats)
    f2h_kernel<<<(CC * 3 * CC) / 8 / 256, 256>>>(w_qkv, wqkvh);
    f2h_kernel<<<(CC * CC) / 8 / 256, 256>>>(w_proj, wprojh);
    f2h_kernel<<<(CC * E4D) / 8 / 256, 256>>>(w1, w1h);
    f2h_kernel<<<(E4D * CC) / 8 / 256, 256>>>(w2, w2h);

    // 1) LN1 (shift dropped: SHIFT==WS so rolls cancel with window partition)
    ln_kernel<<<NTOK, 256>>>(x, ln1_g, ln1_b, n1h);
    // 2) qkv = n1 @ w_qkv + b_qkv           [32768 x 1536] fp16 out
    gemm_h<0,true><<<dim3(1536 / 256, NTOK / 128), 512, SMEM_TOTAL>>>(n1h, wqkvh, b_qkv, nullptr, qkvh, CC, 3 * CC);
    // 3) window attention (512 windows x 16 heads)
    attn_kernel<<<512 * NHEADS, 64>>>(qkvh, atth);
    // 4) msa = att @ w_proj + b_proj + x    [32768 x 512] fp32 out
    gemm_h<1,false><<<dim3(CC / 256, NTOK / 128), 512, SMEM_TOTAL>>>(atth, wprojh, b_proj, x, msa, CC, CC);
    // 5) LN2
    ln_kernel<<<NTOK, 256>>>(msa, ln2_g, ln2_b, n1h);
    // 6) act = gelu(n1 @ w1 + b1)           [32768 x 2048] fp16 out
    gemm_h<2,true><<<dim3(E4D / 256, NTOK / 128), 512, SMEM_TOTAL>>>(n1h, w1h, b1, nullptr, acth, CC, E4D);
    // 7) out = act @ w2 + b2 + msa          [32768 x 512] fp32 out
    gemm_h<1,false><<<dim3(CC / 256, NTOK / 128), 512, SMEM_TOTAL>>>(acth, w2h, b2, msa, out, E4D, CC);
}

// round 9
// speedup vs baseline: 1.8260x; 1.0580x over previous
#include <cuda_runtime.h>
#include <cuda_fp16.h>
#include <cstdint>

#define BB 8
#define HH 64
#define WW 64
#define CC 512
#define NTOK (BB*HH*WW)        /* 32768 tokens */
#define E4D 2048
#define NHEADS 16
#define HD 32

// ---------------- GEMM tile config ------------------------------------------
// block tile 128 x 256, KC=128, 16 warps (512 thr), warp tile 32x64
// fp16 mma.m16n8k16, ldmatrix feeds, 2-stage cp.async pipeline
#define KC 128
#define NSTG 2
#define A_BYTES 32768          /* 128 rows x 256B */
#define B_BYTES 65536          /* 128 k-rows x 512B */
#define STAGE_BYTES (A_BYTES + B_BYTES)        /* 98304 */
#define SMEM_TOTAL (NSTG * STAGE_BYTES)        /* 196608 */

// ---------------- scratch (device globals) ----------------------------------
__device__ __align__(16) __half g_n1h [(size_t)NTOK * CC];
__device__ __align__(16) __half g_qkvh[(size_t)NTOK * 3 * CC];
__device__ __align__(16) __half g_atth[(size_t)NTOK * CC];
__device__ __align__(16) __half g_acth[(size_t)NTOK * E4D];
__device__ float g_msa[(size_t)NTOK * CC];
__device__ __align__(16) __half g_wqkvh[(size_t)CC * 3 * CC];
__device__ __align__(16) __half g_wprojh[(size_t)CC * CC];
__device__ __align__(16) __half g_w1h[(size_t)CC * E4D];
__device__ __align__(16) __half g_w2h[(size_t)E4D * CC];

// ---------------- helpers ----------------------------------------------------
__device__ __forceinline__ uint32_t s2u(const void* p) {
    uint32_t a;
    asm("{ .reg .u64 t; cvta.to.shared.u64 t, %1; cvt.u32.u64 %0, t; }" : "=r"(a) : "l"(p));
    return a;
}
__device__ __forceinline__ void cpa16(uint32_t dst, const void* src) {
    asm volatile("cp.async.cg.shared.global [%0], [%1], 16;" :: "r"(dst), "l"(src));
}
#define CP_COMMIT() asm volatile("cp.async.commit_group;" ::: "memory")
#define CP_WAIT0()  asm volatile("cp.async.wait_group 0;" ::: "memory")

__device__ __forceinline__ void ldsm4(uint32_t* r, uint32_t addr) {
    asm volatile("ldmatrix.sync.aligned.m8n8.x4.shared.b16 {%0,%1,%2,%3}, [%4];"
        : "=r"(r[0]), "=r"(r[1]), "=r"(r[2]), "=r"(r[3]) : "r"(addr));
}
__device__ __forceinline__ void ldsm4t(uint32_t* r, uint32_t addr) {
    asm volatile("ldmatrix.sync.aligned.m8n8.x4.trans.shared.b16 {%0,%1,%2,%3}, [%4];"
        : "=r"(r[0]), "=r"(r[1]), "=r"(r[2]), "=r"(r[3]) : "r"(addr));
}
__device__ __forceinline__ void mma16816(float* c, const uint32_t* a, const uint32_t* b) {
    asm volatile(
        "mma.sync.aligned.m16n8k16.row.col.f32.f16.f16.f32 "
        "{%0,%1,%2,%3}, {%4,%5,%6,%7}, {%8,%9}, {%0,%1,%2,%3};"
        : "+f"(c[0]), "+f"(c[1]), "+f"(c[2]), "+f"(c[3])
        : "r"(a[0]), "r"(a[1]), "r"(a[2]), "r"(a[3]), "r"(b[0]), "r"(b[1]));
}

// ---------------- chunk loader (fp16, XOR-swizzled smem) ---------------------
__device__ __forceinline__ void load_chunk(uint32_t sb, int s, int ci, int tid,
                                           const __half* __restrict__ A,
                                           const __half* __restrict__ W,
                                           size_t rowBase, int colBase, int K, int M) {
    int kt = ci * KC;
    uint32_t Ab = sb + (uint32_t)(s * STAGE_BYTES);
    uint32_t Bb = Ab + A_BYTES;
    // A: 128 rows x 128 fp16 (256B rows, 16 granules, low3(g) ^= row&7)
    #pragma unroll
    for (int i = 0; i < 4; i++) {
        int u = tid + i * 512;
        int r = u >> 4, g = u & 15;
        cpa16(Ab + (uint32_t)(r * 256 + ((g ^ (r & 7)) << 4)),
              A + (rowBase + r) * (size_t)K + kt + g * 8);
    }
    // B: 128 k-rows x 256 fp16 (512B rows, 32 granules, low3(gn) ^= k&7)
    #pragma unroll
    for (int i = 0; i < 8; i++) {
        int u = tid + i * 512;
        int k = u >> 5, gn = u & 31;
        cpa16(Bb + (uint32_t)(k * 512 + ((gn ^ (k & 7)) << 4)),
              W + (size_t)(kt + k) * M + colBase + gn * 8);
    }
    CP_COMMIT();
}

// ---------------- fp16 mma GEMM ----------------------------------------------
// out[N,M] = A[N,K] @ W[K,M] + epilogue. EPI: 0 bias, 1 bias+res, 2 bias+GELU
// OUTH: write __half output (else float)
template<int EPI, bool OUTH>
__global__ __launch_bounds__(512, 1)
void gemm_h(const __half* __restrict__ A, const __half* __restrict__ W,
            const float* __restrict__ bias, const float* __restrict__ res,
            void* __restrict__ outp, int K, int M) {
    extern __shared__ __align__(16) char smem[];
    uint32_t sb = s2u(smem);
    int tid  = threadIdx.x;
    int lane = tid & 31;
    int warp = tid >> 5;
    int wm = warp & 3;               // 4 warps x 32 rows = 128
    int wn = warp >> 2;              // 4 warps x 64 cols = 256
    size_t rowBase = (size_t)blockIdx.y * 128;
    int    colBase = blockIdx.x * 256;
    int nchunk = K / KC;

    float c[2][8][4];
    #pragma unroll
    for (int i = 0; i < 2; i++)
        #pragma unroll
        for (int j = 0; j < 8; j++)
            #pragma unroll
            for (int k = 0; k < 4; k++) c[i][j][k] = 0.f;

    load_chunk(sb, 0, 0, tid, A, W, rowBase, colBase, K, M);

    for (int ci = 0; ci < nchunk; ci++) {
        int s = ci & 1;
        CP_WAIT0();            // chunk ci resident
        __syncthreads();       // all warps done reading stage s (from iter ci-2)
        if (ci + 1 < nchunk)   // overlap next load with this chunk's MMAs
            load_chunk(sb, s ^ 1, ci + 1, tid, A, W, rowBase, colBase, K, M);

        uint32_t Ab = sb + (uint32_t)(s * STAGE_BYTES);
        uint32_t Bb = Ab + A_BYTES;

        #pragma unroll
        for (int ks = 0; ks < 8; ks++) {
            uint32_t a[2][4];
            #pragma unroll
            for (int mt = 0; mt < 2; mt++) {
                int row = wm * 32 + mt * 16 + (lane & 15);
                int g = 2 * ks + (lane >> 4);
                ldsm4(a[mt], Ab + (uint32_t)(row * 256 + ((g ^ (row & 7)) << 4)));
            }
            uint32_t b[8][2];
            #pragma unroll
            for (int pr = 0; pr < 4; pr++) {
                int krow = ks * 16 + (lane & 7) + (((lane >> 3) & 1) << 3);
                int gn = wn * 8 + pr * 2 + (lane >> 4);
                uint32_t t[4];
                ldsm4t(t, Bb + (uint32_t)(krow * 512 + ((gn ^ (krow & 7)) << 4)));
                b[2*pr][0] = t[0]; b[2*pr][1] = t[1];
                b[2*pr+1][0] = t[2]; b[2*pr+1][1] = t[3];
            }
            #pragma unroll
            for (int mt = 0; mt < 2; mt++)
                #pragma unroll
                for (int nt = 0; nt < 8; nt++)
                    mma16816(c[mt][nt], a[mt], b[nt]);
        }
    }

    // ---------------- epilogue ----------------
    #pragma unroll
    for (int mt = 0; mt < 2; mt++) {
        int r0 = wm * 32 + mt * 16 + (lane >> 2);
        #pragma unroll
        for (int nt = 0; nt < 8; nt++) {
            int col = colBase + wn * 64 + nt * 8 + 2 * (lane & 3);
            float2 bv = *(const float2*)(bias + col);
            #pragma unroll
            for (int half = 0; half < 2; half++) {
                size_t row = rowBase + r0 + half * 8;
                float v0 = c[mt][nt][half * 2 + 0] + bv.x;
                float v1 = c[mt][nt][half * 2 + 1] + bv.y;
                if (EPI == 1) {
                    float2 rv = *(const float2*)(res + row * (size_t)M + col);
                    v0 += rv.x; v1 += rv.y;
                }
                if (EPI == 2) {
                    v0 = 0.5f * v0 * (1.f + erff(v0 * 0.70710678118f));
                    v1 = 0.5f * v1 * (1.f + erff(v1 * 0.70710678118f));
                }
                if (OUTH) {
                    *(__half2*)((__half*)outp + row * (size_t)M + col) =
                        __floats2half2_rn(v0, v1);
                } else {
                    float2 ov; ov.x = v0; ov.y = v1;
                    *(float2*)((float*)outp + row * (size_t)M + col) = ov;
                }
            }
        }
    }
}

// ---------------- fp32 -> fp16 convert (all 4 weight tensors in one) ---------
#define W0E ((CC * 3 * CC) / 8)            /* 98304  */
#define W1E (W0E + (CC * CC) / 8)          /* 131072 */
#define W2E (W1E + (CC * E4D) / 8)         /* 262144 */
#define W3E (W2E + (E4D * CC) / 8)         /* 393216 */
__global__ void f2h_all(const float* __restrict__ s0, __half* __restrict__ d0,
                        const float* __restrict__ s1, __half* __restrict__ d1,
                        const float* __restrict__ s2, __half* __restrict__ d2,
                        const float* __restrict__ s3, __half* __restrict__ d3) {
    int idx = blockIdx.x * blockDim.x + threadIdx.x;   // 8 floats per thread
    const float* in; __half* out; int base;
    if      (idx < W0E) { in = s0; out = d0; base = 0;   }
    else if (idx < W1E) { in = s1; out = d1; base = W0E; }
    else if (idx < W2E) { in = s2; out = d2; base = W1E; }
    else                { in = s3; out = d3; base = W2E; }
    int li = idx - base;
    const float4* i4 = (const float4*)in;
    float4 v0 = i4[2 * li], v1 = i4[2 * li + 1];
    __half2* o2 = (__half2*)out + 4 * li;
    o2[0] = __floats2half2_rn(v0.x, v0.y);
    o2[1] = __floats2half2_rn(v0.z, v0.w);
    o2[2] = __floats2half2_rn(v1.x, v1.y);
    o2[3] = __floats2half2_rn(v1.z, v1.w);
}

// ---------------- LayerNorm (fp32 in, fp16 out) ------------------------------
__global__ void ln_kernel(const float* __restrict__ in,
                          const float* __restrict__ g,
                          const float* __restrict__ b,
                          __half* __restrict__ out) {
    int row = blockIdx.x;
    int tid = threadIdx.x;
    const float2* xr = (const float2*)(in + (size_t)row * CC);
    float2 v = xr[tid];
    float s  = v.x + v.y;
    float sq = v.x * v.x + v.y * v.y;
    #pragma unroll
    for (int o = 16; o; o >>= 1) {
        s  += __shfl_xor_sync(0xffffffffu, s,  o);
        sq += __shfl_xor_sync(0xffffffffu, sq, o);
    }
    __shared__ float ss[8], sqq[8];
    int w = tid >> 5, l = tid & 31;
    if (!l) { ss[w] = s; sqq[w] = sq; }
    __syncthreads();
    s = 0.f; sq = 0.f;
    #pragma unroll
    for (int i = 0; i < 8; i++) { s += ss[i]; sq += sqq[i]; }
    float mean = s * (1.f / CC);
    float var  = sq * (1.f / CC) - mean * mean;
    float rstd = rsqrtf(var + 1e-5f);
    float2 gg = ((const float2*)g)[tid];
    float2 bb = ((const float2*)b)[tid];
    float ox = (v.x - mean) * rstd * gg.x + bb.x;
    float oy = (v.y - mean) * rstd * gg.y + bb.y;
    ((__half2*)(out + (size_t)row * CC))[tid] = __floats2half2_rn(ox, oy);
}

// ---------------- window attention (fp16 in/out, fp32 math) ------------------
__device__ __forceinline__ void h8f(uint4 v, float* d) {
    __half2* h = (__half2*)&v;
    #pragma unroll
    for (int j = 0; j < 4; j++) {
        float2 f = __half22float2(h[j]);
        d[2*j] = f.x; d[2*j+1] = f.y;
    }
}

__global__ __launch_bounds__(64)
void attn_kernel(const __half* __restrict__ qkv, __half* __restrict__ out) {
    int blk  = blockIdx.x;
    int head = blk & (NHEADS - 1);
    int win  = blk >> 4;
    int b  = win >> 6;
    int wi = (win >> 3) & 7;
    int wj = win & 7;
    int p = threadIdx.x;
    int r = p >> 3, cc = p & 7;
    int t = b * (HH * WW) + (wi * 8 + r) * WW + wj * 8 + cc;

    __shared__ float Ks[64][33];
    __shared__ float Vs[64][33];

    const uint4* base = (const uint4*)(qkv + (size_t)t * (3 * CC) + head * 96);
    float q[HD];
    #pragma unroll
    for (int i = 0; i < 4; i++) {
        h8f(base[i], q + 8 * i);
        float tmp[8];
        h8f(base[4 + i], tmp);
        #pragma unroll
        for (int j = 0; j < 8; j++) Ks[p][8*i + j] = tmp[j];
        h8f(base[8 + i], tmp);
        #pragma unroll
        for (int j = 0; j < 8; j++) Vs[p][8*i + j] = tmp[j];
    }
    __syncthreads();

    const float scale = 0.17677669529663688f;
    float s[64];
    float mx = -1e30f;
    #pragma unroll 4
    for (int j = 0; j < 64; j++) {
        float acc = 0.f;
        #pragma unroll
        for (int d = 0; d < HD; d++) acc += q[d] * Ks[j][d];
        acc *= scale;
        s[j] = acc;
        mx = fmaxf(mx, acc);
    }
    float sum = 0.f;
    #pragma unroll 4
    for (int j = 0; j < 64; j++) {
        float e = __expf(s[j] - mx);
        s[j] = e;
        sum += e;
    }
    float inv = 1.f / sum;

    float o[HD];
    #pragma unroll
    for (int d = 0; d < HD; d++) o[d] = 0.f;
    #pragma unroll 4
    for (int j = 0; j < 64; j++) {
        float pj = s[j] * inv;
        #pragma unroll
        for (int d = 0; d < HD; d++) o[d] += pj * Vs[j][d];
    }

    __half2* op = (__half2*)(out + (size_t)t * CC + head * HD);
    #pragma unroll
    for (int i = 0; i < 16; i++)
        op[i] = __floats2half2_rn(o[2*i], o[2*i+1]);
}

// ---------------- launch -----------------------------------------------------
extern "C" void kernel_launch(void* const* d_in, const int* in_sizes, int n_in,
                              void* d_out, int out_size) {
    const float* x      = (const float*)d_in[0];
    const float* ln1_g  = (const float*)d_in[1];
    const float* ln1_b  = (const float*)d_in[2];
    const float* w_qkv  = (const float*)d_in[3];
    const float* b_qkv  = (const float*)d_in[4];
    const float* w_proj = (const float*)d_in[5];
    const float* b_proj = (const float*)d_in[6];
    const float* ln2_g  = (const float*)d_in[7];
    const float* ln2_b  = (const float*)d_in[8];
    const float* w1     = (const float*)d_in[9];
    const float* b1     = (const float*)d_in[10];
    const float* w2     = (const float*)d_in[11];
    const float* b2     = (const float*)d_in[12];
    float* out = (float*)d_out;

    __half *n1h, *qkvh, *atth, *acth, *wqkvh, *wprojh, *w1h, *w2h;
    float* msa;
    cudaGetSymbolAddress((void**)&n1h,   g_n1h);
    cudaGetSymbolAddress((void**)&qkvh,  g_qkvh);
    cudaGetSymbolAddress((void**)&atth,  g_atth);
    cudaGetSymbolAddress((void**)&acth,  g_acth);
    cudaGetSymbolAddress((void**)&msa,   g_msa);
    cudaGetSymbolAddress((void**)&wqkvh, g_wqkvh);
    cudaGetSymbolAddress((void**)&wprojh,g_wprojh);
    cudaGetSymbolAddress((void**)&w1h,   g_w1h);
    cudaGetSymbolAddress((void**)&w2h,   g_w2h);

    cudaFuncSetAttribute(gemm_h<0,true >, cudaFuncAttributeMaxDynamicSharedMemorySize, SMEM_TOTAL);
    cudaFuncSetAttribute(gemm_h<1,false>, cudaFuncAttributeMaxDynamicSharedMemorySize, SMEM_TOTAL);
    cudaFuncSetAttribute(gemm_h<2,true >, cudaFuncAttributeMaxDynamicSharedMemorySize, SMEM_TOTAL);

    // 0) all weights -> fp16 in one launch
    f2h_all<<<W3E / 256, 256>>>(w_qkv, wqkvh, w_proj, wprojh, w1, w1h, w2, w2h);

    // 1) LN1 (shift dropped: SHIFT==WS so rolls cancel with window partition)
    ln_kernel<<<NTOK, 256>>>(x, ln1_g, ln1_b, n1h);
    // 2) qkv = n1 @ w_qkv + b_qkv           [32768 x 1536] fp16 out
    gemm_h<0,true><<<dim3(1536 / 256, NTOK / 128), 512, SMEM_TOTAL>>>(n1h, wqkvh, b_qkv, nullptr, qkvh, CC, 3 * CC);
    // 3) window attention (512 windows x 16 heads)
    attn_kernel<<<512 * NHEADS, 64>>>(qkvh, atth);
    // 4) msa = att @ w_proj + b_proj + x    [32768 x 512] fp32 out
    gemm_h<1,false><<<dim3(CC / 256, NTOK / 128), 512, SMEM_TOTAL>>>(atth, wprojh, b_proj, x, msa, CC, CC);
    // 5) LN2
    ln_kernel<<<NTOK, 256>>>(msa, ln2_g, ln2_b, n1h);
    // 6) act = gelu(n1 @ w1 + b1)           [32768 x 2048] fp16 out
    gemm_h<2,true><<<dim3(E4D / 256, NTOK / 128), 512, SMEM_TOTAL>>>(n1h, w1h, b1, nullptr, acth, CC, E4D);
    // 7) out = act @ w2 + b2 + msa          [32768 x 512] fp32 out
    gemm_h<1,false><<<dim3(CC / 256, NTOK / 128), 512, SMEM_TOTAL>>>(acth, w2h, b2, msa, out, E4D, CC);
}

// round 10
// speedup vs baseline: 2.2434x; 1.2285x over previous
#include <cuda_runtime.h>
#include <cuda_fp16.h>
#include <cstdint>

#define BB 8
#define HH 64
#define WW 64
#define CC 512
#define NTOK (BB*HH*WW)        /* 32768 tokens */
#define E4D 2048
#define NHEADS 16
#define HD 32

// ---------------- GEMM tile config ------------------------------------------
#define KC 128
#define NSTG 2
#define A_BYTES 32768          /* 128 rows x 256B */
#define B_BYTES 65536          /* 128 k-rows x 512B */
#define STAGE_BYTES (A_BYTES + B_BYTES)        /* 98304 */
#define SMEM_TOTAL (NSTG * STAGE_BYTES)        /* 196608 */

// ---------------- scratch (device globals) ----------------------------------
__device__ __align__(16) __half g_n1h [(size_t)NTOK * CC];
__device__ __align__(16) __half g_qkvh[(size_t)NTOK * 3 * CC];
__device__ __align__(16) __half g_atth[(size_t)NTOK * CC];
__device__ __align__(16) __half g_acth[(size_t)NTOK * E4D];
__device__ float g_msa[(size_t)NTOK * CC];
__device__ __align__(16) __half g_wqkvh[(size_t)CC * 3 * CC];
__device__ __align__(16) __half g_wprojh[(size_t)CC * CC];
__device__ __align__(16) __half g_w1h[(size_t)CC * E4D];
__device__ __align__(16) __half g_w2h[(size_t)E4D * CC];

// ---------------- helpers ----------------------------------------------------
__device__ __forceinline__ uint32_t s2u(const void* p) {
    uint32_t a;
    asm("{ .reg .u64 t; cvta.to.shared.u64 t, %1; cvt.u32.u64 %0, t; }" : "=r"(a) : "l"(p));
    return a;
}
__device__ __forceinline__ void cpa16(uint32_t dst, const void* src) {
    asm volatile("cp.async.cg.shared.global [%0], [%1], 16;" :: "r"(dst), "l"(src));
}
#define CP_COMMIT() asm volatile("cp.async.commit_group;" ::: "memory")
#define CP_WAIT0()  asm volatile("cp.async.wait_group 0;" ::: "memory")

__device__ __forceinline__ void ldsm4(uint32_t* r, uint32_t addr) {
    asm volatile("ldmatrix.sync.aligned.m8n8.x4.shared.b16 {%0,%1,%2,%3}, [%4];"
        : "=r"(r[0]), "=r"(r[1]), "=r"(r[2]), "=r"(r[3]) : "r"(addr));
}
__device__ __forceinline__ void ldsm4t(uint32_t* r, uint32_t addr) {
    asm volatile("ldmatrix.sync.aligned.m8n8.x4.trans.shared.b16 {%0,%1,%2,%3}, [%4];"
        : "=r"(r[0]), "=r"(r[1]), "=r"(r[2]), "=r"(r[3]) : "r"(addr));
}
__device__ __forceinline__ void mma16816(float* c, const uint32_t* a, const uint32_t* b) {
    asm volatile(
        "mma.sync.aligned.m16n8k16.row.col.f32.f16.f16.f32 "
        "{%0,%1,%2,%3}, {%4,%5,%6,%7}, {%8,%9}, {%0,%1,%2,%3};"
        : "+f"(c[0]), "+f"(c[1]), "+f"(c[2]), "+f"(c[3])
        : "r"(a[0]), "r"(a[1]), "r"(a[2]), "r"(a[3]), "r"(b[0]), "r"(b[1]));
}

// ---------------- chunk loader (fp16, XOR-swizzled smem) ---------------------
__device__ __forceinline__ void load_chunk(uint32_t sb, int s, int ci, int tid,
                                           const __half* __restrict__ A,
                                           const __half* __restrict__ W,
                                           size_t rowBase, int colBase, int K, int M) {
    int kt = ci * KC;
    uint32_t Ab = sb + (uint32_t)(s * STAGE_BYTES);
    uint32_t Bb = Ab + A_BYTES;
    #pragma unroll
    for (int i = 0; i < 4; i++) {
        int u = tid + i * 512;
        int r = u >> 4, g = u & 15;
        cpa16(Ab + (uint32_t)(r * 256 + ((g ^ (r & 7)) << 4)),
              A + (rowBase + r) * (size_t)K + kt + g * 8);
    }
    #pragma unroll
    for (int i = 0; i < 8; i++) {
        int u = tid + i * 512;
        int k = u >> 5, gn = u & 31;
        cpa16(Bb + (uint32_t)(k * 512 + ((gn ^ (k & 7)) << 4)),
              W + (size_t)(kt + k) * M + colBase + gn * 8);
    }
    CP_COMMIT();
}

// ---------------- fp16 mma GEMM ----------------------------------------------
template<int EPI, bool OUTH>
__global__ __launch_bounds__(512, 1)
void gemm_h(const __half* __restrict__ A, const __half* __restrict__ W,
            const float* __restrict__ bias, const float* __restrict__ res,
            void* __restrict__ outp, int K, int M) {
    extern __shared__ __align__(16) char smem[];
    uint32_t sb = s2u(smem);
    int tid  = threadIdx.x;
    int lane = tid & 31;
    int warp = tid >> 5;
    int wm = warp & 3;
    int wn = warp >> 2;
    size_t rowBase = (size_t)blockIdx.y * 128;
    int    colBase = blockIdx.x * 256;
    int nchunk = K / KC;

    float c[2][8][4];
    #pragma unroll
    for (int i = 0; i < 2; i++)
        #pragma unroll
        for (int j = 0; j < 8; j++)
            #pragma unroll
            for (int k = 0; k < 4; k++) c[i][j][k] = 0.f;

    load_chunk(sb, 0, 0, tid, A, W, rowBase, colBase, K, M);

    for (int ci = 0; ci < nchunk; ci++) {
        int s = ci & 1;
        CP_WAIT0();
        __syncthreads();
        if (ci + 1 < nchunk)
            load_chunk(sb, s ^ 1, ci + 1, tid, A, W, rowBase, colBase, K, M);

        uint32_t Ab = sb + (uint32_t)(s * STAGE_BYTES);
        uint32_t Bb = Ab + A_BYTES;

        #pragma unroll
        for (int ks = 0; ks < 8; ks++) {
            uint32_t a[2][4];
            #pragma unroll
            for (int mt = 0; mt < 2; mt++) {
                int row = wm * 32 + mt * 16 + (lane & 15);
                int g = 2 * ks + (lane >> 4);
                ldsm4(a[mt], Ab + (uint32_t)(row * 256 + ((g ^ (row & 7)) << 4)));
            }
            uint32_t b[8][2];
            #pragma unroll
            for (int pr = 0; pr < 4; pr++) {
                int krow = ks * 16 + (lane & 7) + (((lane >> 3) & 1) << 3);
                int gn = wn * 8 + pr * 2 + (lane >> 4);
                uint32_t t[4];
                ldsm4t(t, Bb + (uint32_t)(krow * 512 + ((gn ^ (krow & 7)) << 4)));
                b[2*pr][0] = t[0]; b[2*pr][1] = t[1];
                b[2*pr+1][0] = t[2]; b[2*pr+1][1] = t[3];
            }
            #pragma unroll
            for (int mt = 0; mt < 2; mt++)
                #pragma unroll
                for (int nt = 0; nt < 8; nt++)
                    mma16816(c[mt][nt], a[mt], b[nt]);
        }
    }

    #pragma unroll
    for (int mt = 0; mt < 2; mt++) {
        int r0 = wm * 32 + mt * 16 + (lane >> 2);
        #pragma unroll
        for (int nt = 0; nt < 8; nt++) {
            int col = colBase + wn * 64 + nt * 8 + 2 * (lane & 3);
            float2 bv = *(const float2*)(bias + col);
            #pragma unroll
            for (int half = 0; half < 2; half++) {
                size_t row = rowBase + r0 + half * 8;
                float v0 = c[mt][nt][half * 2 + 0] + bv.x;
                float v1 = c[mt][nt][half * 2 + 1] + bv.y;
                if (EPI == 1) {
                    float2 rv = *(const float2*)(res + row * (size_t)M + col);
                    v0 += rv.x; v1 += rv.y;
                }
                if (EPI == 2) {
                    v0 = 0.5f * v0 * (1.f + erff(v0 * 0.70710678118f));
                    v1 = 0.5f * v1 * (1.f + erff(v1 * 0.70710678118f));
                }
                if (OUTH) {
                    *(__half2*)((__half*)outp + row * (size_t)M + col) =
                        __floats2half2_rn(v0, v1);
                } else {
                    float2 ov; ov.x = v0; ov.y = v1;
                    *(float2*)((float*)outp + row * (size_t)M + col) = ov;
                }
            }
        }
    }
}

// ---------------- fp32 -> fp16 convert (all 4 weight tensors in one) ---------
#define W0E ((CC * 3 * CC) / 8)
#define W1E (W0E + (CC * CC) / 8)
#define W2E (W1E + (CC * E4D) / 8)
#define W3E (W2E + (E4D * CC) / 8)
__global__ void f2h_all(const float* __restrict__ s0, __half* __restrict__ d0,
                        const float* __restrict__ s1, __half* __restrict__ d1,
                        const float* __restrict__ s2, __half* __restrict__ d2,
                        const float* __restrict__ s3, __half* __restrict__ d3) {
    int idx = blockIdx.x * blockDim.x + threadIdx.x;
    const float* in; __half* out; int base;
    if      (idx < W0E) { in = s0; out = d0; base = 0;   }
    else if (idx < W1E) { in = s1; out = d1; base = W0E; }
    else if (idx < W2E) { in = s2; out = d2; base = W1E; }
    else                { in = s3; out = d3; base = W2E; }
    int li = idx - base;
    const float4* i4 = (const float4*)in;
    float4 v0 = i4[2 * li], v1 = i4[2 * li + 1];
    __half2* o2 = (__half2*)out + 4 * li;
    o2[0] = __floats2half2_rn(v0.x, v0.y);
    o2[1] = __floats2half2_rn(v0.z, v0.w);
    o2[2] = __floats2half2_rn(v1.x, v1.y);
    o2[3] = __floats2half2_rn(v1.z, v1.w);
}

// ---------------- LayerNorm (fp32 in, fp16 out) ------------------------------
__global__ void ln_kernel(const float* __restrict__ in,
                          const float* __restrict__ g,
                          const float* __restrict__ b,
                          __half* __restrict__ out) {
    int row = blockIdx.x;
    int tid = threadIdx.x;
    const float2* xr = (const float2*)(in + (size_t)row * CC);
    float2 v = xr[tid];
    float s  = v.x + v.y;
    float sq = v.x * v.x + v.y * v.y;
    #pragma unroll
    for (int o = 16; o; o >>= 1) {
        s  += __shfl_xor_sync(0xffffffffu, s,  o);
        sq += __shfl_xor_sync(0xffffffffu, sq, o);
    }
    __shared__ float ss[8], sqq[8];
    int w = tid >> 5, l = tid & 31;
    if (!l) { ss[w] = s; sqq[w] = sq; }
    __syncthreads();
    s = 0.f; sq = 0.f;
    #pragma unroll
    for (int i = 0; i < 8; i++) { s += ss[i]; sq += sqq[i]; }
    float mean = s * (1.f / CC);
    float var  = sq * (1.f / CC) - mean * mean;
    float rstd = rsqrtf(var + 1e-5f);
    float2 gg = ((const float2*)g)[tid];
    float2 bb = ((const float2*)b)[tid];
    float ox = (v.x - mean) * rstd * gg.x + bb.x;
    float oy = (v.y - mean) * rstd * gg.y + bb.y;
    ((__half2*)(out + (size_t)row * CC))[tid] = __floats2half2_rn(ox, oy);
}

// ---------------- tensor-core window attention -------------------------------
// one block (128 thr, 4 warps) per (window, head); warp w -> q rows 16w..16w+15
// smem: Q/K/V each 64 tokens x 32 dims fp16, 64B rows, swizzle g ^ ((row>>1)&3)
__global__ __launch_bounds__(128)
void attn_mma(const __half* __restrict__ qkv, __half* __restrict__ out) {
    int blk  = blockIdx.x;
    int head = blk & (NHEADS - 1);
    int win  = blk >> 4;
    int b  = win >> 6;
    int wi = (win >> 3) & 7;
    int wj = win & 7;
    int tid  = threadIdx.x;
    int lane = tid & 31;
    int warp = tid >> 5;

    __shared__ __align__(16) __half sm[3 * 64 * 32];
    uint32_t sb = s2u(sm);          // Q at +0, K at +4096, V at +8192 (bytes)

    // ---- load Q,K,V (768 x 16B granules, 6 per thread) ----
    #pragma unroll
    for (int i = 0; i < 6; i++) {
        int G = tid + i * 128;
        int tensor = G >> 8;          // 0=Q 1=K 2=V
        int rem = G & 255;
        int tok = rem >> 2;           // window-local token 0..63
        int g   = rem & 3;
        int tg  = b * (HH * WW) + (wi * 8 + (tok >> 3)) * WW + wj * 8 + (tok & 7);
        cpa16(sb + tensor * 4096 + tok * 64 + ((g ^ ((tok >> 1) & 3)) << 4),
              qkv + (size_t)tg * (3 * CC) + head * 96 + tensor * 32 + g * 8);
    }
    CP_COMMIT();
    CP_WAIT0();
    __syncthreads();

    int q0 = warp * 16;

    // ---- S = Q K^T  (16 x 64), fp32 accum ----
    float c[8][4];
    #pragma unroll
    for (int t = 0; t < 8; t++)
        #pragma unroll
        for (int j = 0; j < 4; j++) c[t][j] = 0.f;

    #pragma unroll
    for (int ks = 0; ks < 2; ks++) {
        uint32_t a[4];
        {
            int row = q0 + (lane & 15);
            int g = 2 * ks + (lane >> 4);
            ldsm4(a, sb + row * 64 + ((g ^ ((row >> 1) & 3)) << 4));
        }
        #pragma unroll
        for (int np = 0; np < 4; np++) {
            uint32_t kb[4];
            int tok = 16 * np + (((lane >> 4) & 1) << 3) + (lane & 7);
            int g = 2 * ks + ((lane >> 3) & 1);
            ldsm4(kb, sb + 4096 + tok * 64 + ((g ^ ((tok >> 1) & 3)) << 4));
            mma16816(c[2 * np],     a, kb);
            mma16816(c[2 * np + 1], a, kb + 2);
        }
    }

    // ---- softmax (rows l>>2 and l>>2+8; quad shuffles) ----
    const float scale = 0.17677669529663688f;   // 32^-0.5
    float mLo = -1e30f, mHi = -1e30f;
    #pragma unroll
    for (int t = 0; t < 8; t++) {
        mLo = fmaxf(mLo, fmaxf(c[t][0], c[t][1]));
        mHi = fmaxf(mHi, fmaxf(c[t][2], c[t][3]));
    }
    #pragma unroll
    for (int off = 1; off <= 2; off <<= 1) {
        mLo = fmaxf(mLo, __shfl_xor_sync(0xffffffffu, mLo, off));
        mHi = fmaxf(mHi, __shfl_xor_sync(0xffffffffu, mHi, off));
    }
    float sLo = 0.f, sHi = 0.f;
    #pragma unroll
    for (int t = 0; t < 8; t++) {
        c[t][0] = __expf((c[t][0] - mLo) * scale);
        c[t][1] = __expf((c[t][1] - mLo) * scale);
        c[t][2] = __expf((c[t][2] - mHi) * scale);
        c[t][3] = __expf((c[t][3] - mHi) * scale);
        sLo += c[t][0] + c[t][1];
        sHi += c[t][2] + c[t][3];
    }
    #pragma unroll
    for (int off = 1; off <= 2; off <<= 1) {
        sLo += __shfl_xor_sync(0xffffffffu, sLo, off);
        sHi += __shfl_xor_sync(0xffffffffu, sHi, off);
    }
    float iLo = 1.f / sLo, iHi = 1.f / sHi;

    // ---- P (fp16 A-fragments) ----
    uint32_t pa[4][4];
    #pragma unroll
    for (int kt = 0; kt < 4; kt++) {
        __half2 h0 = __floats2half2_rn(c[2*kt][0] * iLo, c[2*kt][1] * iLo);
        __half2 h1 = __floats2half2_rn(c[2*kt][2] * iHi, c[2*kt][3] * iHi);
        __half2 h2 = __floats2half2_rn(c[2*kt+1][0] * iLo, c[2*kt+1][1] * iLo);
        __half2 h3 = __floats2half2_rn(c[2*kt+1][2] * iHi, c[2*kt+1][3] * iHi);
        pa[kt][0] = *(uint32_t*)&h0;
        pa[kt][1] = *(uint32_t*)&h1;
        pa[kt][2] = *(uint32_t*)&h2;
        pa[kt][3] = *(uint32_t*)&h3;
    }

    // ---- O = P V  (16 x 32), fp32 accum ----
    float o[4][4];
    #pragma unroll
    for (int nt = 0; nt < 4; nt++)
        #pragma unroll
        for (int j = 0; j < 4; j++) o[nt][j] = 0.f;

    #pragma unroll
    for (int kt = 0; kt < 4; kt++) {
        uint32_t vb[4][2];
        #pragma unroll
        for (int pr = 0; pr < 2; pr++) {
            int tok = kt * 16 + (lane & 7) + (((lane >> 3) & 1) << 3);
            int g = pr * 2 + (lane >> 4);
            uint32_t t4[4];
            ldsm4t(t4, sb + 8192 + tok * 64 + ((g ^ ((tok >> 1) & 3)) << 4));
            vb[2*pr][0] = t4[0]; vb[2*pr][1] = t4[1];
            vb[2*pr+1][0] = t4[2]; vb[2*pr+1][1] = t4[3];
        }
        #pragma unroll
        for (int nt = 0; nt < 4; nt++)
            mma16816(o[nt], pa[kt], vb[nt]);
    }

    // ---- write O (fp16) ----
    #pragma unroll
    for (int half = 0; half < 2; half++) {
        int p = q0 + (lane >> 2) + half * 8;
        int tg = b * (HH * WW) + (wi * 8 + (p >> 3)) * WW + wj * 8 + (p & 7);
        __half* op = out + (size_t)tg * CC + head * HD;
        #pragma unroll
        for (int nt = 0; nt < 4; nt++) {
            __half2 hv = __floats2half2_rn(o[nt][half * 2], o[nt][half * 2 + 1]);
            *(__half2*)(op + nt * 8 + 2 * (lane & 3)) = hv;
        }
    }
}

// ---------------- launch -----------------------------------------------------
extern "C" void kernel_launch(void* const* d_in, const int* in_sizes, int n_in,
                              void* d_out, int out_size) {
    const float* x      = (const float*)d_in[0];
    const float* ln1_g  = (const float*)d_in[1];
    const float* ln1_b  = (const float*)d_in[2];
    const float* w_qkv  = (const float*)d_in[3];
    const float* b_qkv  = (const float*)d_in[4];
    const float* w_proj = (const float*)d_in[5];
    const float* b_proj = (const float*)d_in[6];
    const float* ln2_g  = (const float*)d_in[7];
    const float* ln2_b  = (const float*)d_in[8];
    const float* w1     = (const float*)d_in[9];
    const float* b1     = (const float*)d_in[10];
    const float* w2     = (const float*)d_in[11];
    const float* b2     = (const float*)d_in[12];
    float* out = (float*)d_out;

    __half *n1h, *qkvh, *atth, *acth, *wqkvh, *wprojh, *w1h, *w2h;
    float* msa;
    cudaGetSymbolAddress((void**)&n1h,   g_n1h);
    cudaGetSymbolAddress((void**)&qkvh,  g_qkvh);
    cudaGetSymbolAddress((void**)&atth,  g_atth);
    cudaGetSymbolAddress((void**)&acth,  g_acth);
    cudaGetSymbolAddress((void**)&msa,   g_msa);
    cudaGetSymbolAddress((void**)&wqkvh, g_wqkvh);
    cudaGetSymbolAddress((void**)&wprojh,g_wprojh);
    cudaGetSymbolAddress((void**)&w1h,   g_w1h);
    cudaGetSymbolAddress((void**)&w2h,   g_w2h);

    cudaFuncSetAttribute(gemm_h<0,true >, cudaFuncAttributeMaxDynamicSharedMemorySize, SMEM_TOTAL);
    cudaFuncSetAttribute(gemm_h<1,false>, cudaFuncAttributeMaxDynamicSharedMemorySize, SMEM_TOTAL);
    cudaFuncSetAttribute(gemm_h<2,true >, cudaFuncAttributeMaxDynamicSharedMemorySize, SMEM_TOTAL);

    // 0) all weights -> fp16 in one launch
    f2h_all<<<W3E / 256, 256>>>(w_qkv, wqkvh, w_proj, wprojh, w1, w1h, w2, w2h);

    // 1) LN1 (shift dropped: SHIFT==WS so rolls cancel with window partition)
    ln_kernel<<<NTOK, 256>>>(x, ln1_g, ln1_b, n1h);
    // 2) qkv = n1 @ w_qkv + b_qkv           [32768 x 1536] fp16 out
    gemm_h<0,true><<<dim3(1536 / 256, NTOK / 128), 512, SMEM_TOTAL>>>(n1h, wqkvh, b_qkv, nullptr, qkvh, CC, 3 * CC);
    // 3) tensor-core window attention (512 windows x 16 heads)
    attn_mma<<<512 * NHEADS, 128>>>(qkvh, atth);
    // 4) msa = att @ w_proj + b_proj + x    [32768 x 512] fp32 out
    gemm_h<1,false><<<dim3(CC / 256, NTOK / 128), 512, SMEM_TOTAL>>>(atth, wprojh, b_proj, x, msa, CC, CC);
    // 5) LN2
    ln_kernel<<<NTOK, 256>>>(msa, ln2_g, ln2_b, n1h);
    // 6) act = gelu(n1 @ w1 + b1)           [32768 x 2048] fp16 out
    gemm_h<2,true><<<dim3(E4D / 256, NTOK / 128), 512, SMEM_TOTAL>>>(n1h, w1h, b1, nullptr, acth, CC, E4D);
    // 7) out = act @ w2 + b2 + msa          [32768 x 512] fp32 out
    gemm_h<1,false><<<dim3(CC / 256, NTOK / 128), 512, SMEM_TOTAL>>>(acth, w2h, b2, msa, out, E4D, CC);
}

// round 11
// speedup vs baseline: 2.2455x; 1.0010x over previous
#include <cuda_runtime.h>
#include <cuda_fp16.h>
#include <cstdint>

#define BB 8
#define HH 64
#define WW 64
#define CC 512
#define NTOK (BB*HH*WW)        /* 32768 tokens */
#define E4D 2048
#define NHEADS 16
#define HD 32

// ---------------- GEMM tile config ------------------------------------------
#define KC 128
#define NSTG 2
#define A_BYTES 32768          /* 128 rows x 256B */
#define B_BYTES 65536          /* 128 k-rows x 512B */
#define STAGE_BYTES (A_BYTES + B_BYTES)        /* 98304 */
#define SMEM_TOTAL (NSTG * STAGE_BYTES)        /* 196608 */

// ---------------- scratch (device globals) ----------------------------------
__device__ __align__(16) __half g_n1h [(size_t)NTOK * CC];
__device__ __align__(16) __half g_qkvh[(size_t)NTOK * 3 * CC];
__device__ __align__(16) __half g_atth[(size_t)NTOK * CC];
__device__ __align__(16) __half g_acth[(size_t)NTOK * E4D];
__device__ float g_msa[(size_t)NTOK * CC];
__device__ __align__(16) __half g_wqkvh[(size_t)CC * 3 * CC];
__device__ __align__(16) __half g_wprojh[(size_t)CC * CC];
__device__ __align__(16) __half g_w1h[(size_t)CC * E4D];
__device__ __align__(16) __half g_w2h[(size_t)E4D * CC];

// ---------------- helpers ----------------------------------------------------
__device__ __forceinline__ uint32_t s2u(const void* p) {
    uint32_t a;
    asm("{ .reg .u64 t; cvta.to.shared.u64 t, %1; cvt.u32.u64 %0, t; }" : "=r"(a) : "l"(p));
    return a;
}
__device__ __forceinline__ void cpa16(uint32_t dst, const void* src) {
    asm volatile("cp.async.cg.shared.global [%0], [%1], 16;" :: "r"(dst), "l"(src));
}
#define CP_COMMIT() asm volatile("cp.async.commit_group;" ::: "memory")
#define CP_WAIT0()  asm volatile("cp.async.wait_group 0;" ::: "memory")

__device__ __forceinline__ void ldsm4(uint32_t* r, uint32_t addr) {
    asm volatile("ldmatrix.sync.aligned.m8n8.x4.shared.b16 {%0,%1,%2,%3}, [%4];"
        : "=r"(r[0]), "=r"(r[1]), "=r"(r[2]), "=r"(r[3]) : "r"(addr));
}
__device__ __forceinline__ void ldsm4t(uint32_t* r, uint32_t addr) {
    asm volatile("ldmatrix.sync.aligned.m8n8.x4.trans.shared.b16 {%0,%1,%2,%3}, [%4];"
        : "=r"(r[0]), "=r"(r[1]), "=r"(r[2]), "=r"(r[3]) : "r"(addr));
}
__device__ __forceinline__ void mma16816(float* c, const uint32_t* a, const uint32_t* b) {
    asm volatile(
        "mma.sync.aligned.m16n8k16.row.col.f32.f16.f16.f32 "
        "{%0,%1,%2,%3}, {%4,%5,%6,%7}, {%8,%9}, {%0,%1,%2,%3};"
        : "+f"(c[0]), "+f"(c[1]), "+f"(c[2]), "+f"(c[3])
        : "r"(a[0]), "r"(a[1]), "r"(a[2]), "r"(a[3]), "r"(b[0]), "r"(b[1]));
}

// ---------------- chunk loader (fp16, XOR-swizzled smem) ---------------------
__device__ __forceinline__ void load_chunk(uint32_t sb, int s, int ci, int tid,
                                           const __half* __restrict__ A,
                                           const __half* __restrict__ W,
                                           size_t rowBase, int colBase, int K, int M) {
    int kt = ci * KC;
    uint32_t Ab = sb + (uint32_t)(s * STAGE_BYTES);
    uint32_t Bb = Ab + A_BYTES;
    #pragma unroll
    for (int i = 0; i < 4; i++) {
        int u = tid + i * 512;
        int r = u >> 4, g = u & 15;
        cpa16(Ab + (uint32_t)(r * 256 + ((g ^ (r & 7)) << 4)),
              A + (rowBase + r) * (size_t)K + kt + g * 8);
    }
    #pragma unroll
    for (int i = 0; i < 8; i++) {
        int u = tid + i * 512;
        int k = u >> 5, gn = u & 31;
        cpa16(Bb + (uint32_t)(k * 512 + ((gn ^ (k & 7)) << 4)),
              W + (size_t)(kt + k) * M + colBase + gn * 8);
    }
    CP_COMMIT();
}

// ---------------- fp16 mma GEMM ----------------------------------------------
template<int EPI, bool OUTH>
__global__ __launch_bounds__(512, 1)
void gemm_h(const __half* __restrict__ A, const __half* __restrict__ W,
            const float* __restrict__ bias, const float* __restrict__ res,
            void* __restrict__ outp, int K, int M) {
    extern __shared__ __align__(16) char smem[];
    uint32_t sb = s2u(smem);
    int tid  = threadIdx.x;
    int lane = tid & 31;
    int warp = tid >> 5;
    int wm = warp & 3;
    int wn = warp >> 2;
    size_t rowBase = (size_t)blockIdx.y * 128;
    int    colBase = blockIdx.x * 256;
    int nchunk = K / KC;

    float c[2][8][4];
    #pragma unroll
    for (int i = 0; i < 2; i++)
        #pragma unroll
        for (int j = 0; j < 8; j++)
            #pragma unroll
            for (int k = 0; k < 4; k++) c[i][j][k] = 0.f;

    load_chunk(sb, 0, 0, tid, A, W, rowBase, colBase, K, M);

    for (int ci = 0; ci < nchunk; ci++) {
        int s = ci & 1;
        CP_WAIT0();
        __syncthreads();
        if (ci + 1 < nchunk)
            load_chunk(sb, s ^ 1, ci + 1, tid, A, W, rowBase, colBase, K, M);

        uint32_t Ab = sb + (uint32_t)(s * STAGE_BYTES);
        uint32_t Bb = Ab + A_BYTES;

        #pragma unroll
        for (int ks = 0; ks < 8; ks++) {
            uint32_t a[2][4];
            #pragma unroll
            for (int mt = 0; mt < 2; mt++) {
                int row = wm * 32 + mt * 16 + (lane & 15);
                int g = 2 * ks + (lane >> 4);
                ldsm4(a[mt], Ab + (uint32_t)(row * 256 + ((g ^ (row & 7)) << 4)));
            }
            uint32_t b[8][2];
            #pragma unroll
            for (int pr = 0; pr < 4; pr++) {
                int krow = ks * 16 + (lane & 7) + (((lane >> 3) & 1) << 3);
                int gn = wn * 8 + pr * 2 + (lane >> 4);
                uint32_t t[4];
                ldsm4t(t, Bb + (uint32_t)(krow * 512 + ((gn ^ (krow & 7)) << 4)));
                b[2*pr][0] = t[0]; b[2*pr][1] = t[1];
                b[2*pr+1][0] = t[2]; b[2*pr+1][1] = t[3];
            }
            #pragma unroll
            for (int mt = 0; mt < 2; mt++)
                #pragma unroll
                for (int nt = 0; nt < 8; nt++)
                    mma16816(c[mt][nt], a[mt], b[nt]);
        }
    }

    #pragma unroll
    for (int mt = 0; mt < 2; mt++) {
        int r0 = wm * 32 + mt * 16 + (lane >> 2);
        #pragma unroll
        for (int nt = 0; nt < 8; nt++) {
            int col = colBase + wn * 64 + nt * 8 + 2 * (lane & 3);
            float2 bv = *(const float2*)(bias + col);
            #pragma unroll
            for (int half = 0; half < 2; half++) {
                size_t row = rowBase + r0 + half * 8;
                float v0 = c[mt][nt][half * 2 + 0] + bv.x;
                float v1 = c[mt][nt][half * 2 + 1] + bv.y;
                if (EPI == 1) {
                    float2 rv = *(const float2*)(res + row * (size_t)M + col);
                    v0 += rv.x; v1 += rv.y;
                }
                if (EPI == 2) {
                    v0 = 0.5f * v0 * (1.f + erff(v0 * 0.70710678118f));
                    v1 = 0.5f * v1 * (1.f + erff(v1 * 0.70710678118f));
                }
                if (OUTH) {
                    *(__half2*)((__half*)outp + row * (size_t)M + col) =
                        __floats2half2_rn(v0, v1);
                } else {
                    float2 ov; ov.x = v0; ov.y = v1;
                    *(float2*)((float*)outp + row * (size_t)M + col) = ov;
                }
            }
        }
    }
}

// ---------------- fp32 -> fp16 convert (all 4 weight tensors in one) ---------
#define W0E ((CC * 3 * CC) / 8)
#define W1E (W0E + (CC * CC) / 8)
#define W2E (W1E + (CC * E4D) / 8)
#define W3E (W2E + (E4D * CC) / 8)
__global__ void f2h_all(const float* __restrict__ s0, __half* __restrict__ d0,
                        const float* __restrict__ s1, __half* __restrict__ d1,
                        const float* __restrict__ s2, __half* __restrict__ d2,
                        const float* __restrict__ s3, __half* __restrict__ d3) {
    int idx = blockIdx.x * blockDim.x + threadIdx.x;
    const float* in; __half* out; int base;
    if      (idx < W0E) { in = s0; out = d0; base = 0;   }
    else if (idx < W1E) { in = s1; out = d1; base = W0E; }
    else if (idx < W2E) { in = s2; out = d2; base = W1E; }
    else                { in = s3; out = d3; base = W2E; }
    int li = idx - base;
    const float4* i4 = (const float4*)in;
    float4 v0 = i4[2 * li], v1 = i4[2 * li + 1];
    __half2* o2 = (__half2*)out + 4 * li;
    o2[0] = __floats2half2_rn(v0.x, v0.y);
    o2[1] = __floats2half2_rn(v0.z, v0.w);
    o2[2] = __floats2half2_rn(v1.x, v1.y);
    o2[3] = __floats2half2_rn(v1.z, v1.w);
}

// ---------------- LayerNorm (fp32 in, fp16 out) ------------------------------
__global__ void ln_kernel(const float* __restrict__ in,
                          const float* __restrict__ g,
                          const float* __restrict__ b,
                          __half* __restrict__ out) {
    int row = blockIdx.x;
    int tid = threadIdx.x;
    const float2* xr = (const float2*)(in + (size_t)row * CC);
    float2 v = xr[tid];
    float s  = v.x + v.y;
    float sq = v.x * v.x + v.y * v.y;
    #pragma unroll
    for (int o = 16; o; o >>= 1) {
        s  += __shfl_xor_sync(0xffffffffu, s,  o);
        sq += __shfl_xor_sync(0xffffffffu, sq, o);
    }
    __shared__ float ss[8], sqq[8];
    int w = tid >> 5, l = tid & 31;
    if (!l) { ss[w] = s; sqq[w] = sq; }
    __syncthreads();
    s = 0.f; sq = 0.f;
    #pragma unroll
    for (int i = 0; i < 8; i++) { s += ss[i]; sq += sqq[i]; }
    float mean = s * (1.f / CC);
    float var  = sq * (1.f / CC) - mean * mean;
    float rstd = rsqrtf(var + 1e-5f);
    float2 gg = ((const float2*)g)[tid];
    float2 bb = ((const float2*)b)[tid];
    float ox = (v.x - mean) * rstd * gg.x + bb.x;
    float oy = (v.y - mean) * rstd * gg.y + bb.y;
    ((__half2*)(out + (size_t)row * CC))[tid] = __floats2half2_rn(ox, oy);
}

// ---------------- tensor-core window attention -------------------------------
// one block (128 thr, 4 warps) per (window, head); warp w -> q rows 16w..16w+15
// smem: Q/K/V each 64 tokens x 32 dims fp16, 64B rows, swizzle g ^ ((row>>1)&3)
__global__ __launch_bounds__(128)
void attn_mma(const __half* __restrict__ qkv, __half* __restrict__ out) {
    int blk  = blockIdx.x;
    int head = blk & (NHEADS - 1);
    int win  = blk >> 4;
    int b  = win >> 6;
    int wi = (win >> 3) & 7;
    int wj = win & 7;
    int tid  = threadIdx.x;
    int lane = tid & 31;
    int warp = tid >> 5;

    __shared__ __align__(16) __half sm[3 * 64 * 32];
    uint32_t sb = s2u(sm);          // Q at +0, K at +4096, V at +8192 (bytes)

    // ---- load Q,K,V (768 x 16B granules, 6 per thread) ----
    #pragma unroll
    for (int i = 0; i < 6; i++) {
        int G = tid + i * 128;
        int tensor = G >> 8;          // 0=Q 1=K 2=V
        int rem = G & 255;
        int tok = rem >> 2;           // window-local token 0..63
        int g   = rem & 3;
        int tg  = b * (HH * WW) + (wi * 8 + (tok >> 3)) * WW + wj * 8 + (tok & 7);
        cpa16(sb + tensor * 4096 + tok * 64 + ((g ^ ((tok >> 1) & 3)) << 4),
              qkv + (size_t)tg * (3 * CC) + head * 96 + tensor * 32 + g * 8);
    }
    CP_COMMIT();
    CP_WAIT0();
    __syncthreads();

    int q0 = warp * 16;

    // ---- S = Q K^T  (16 x 64), fp32 accum ----
    float c[8][4];
    #pragma unroll
    for (int t = 0; t < 8; t++)
        #pragma unroll
        for (int j = 0; j < 4; j++) c[t][j] = 0.f;

    #pragma unroll
    for (int ks = 0; ks < 2; ks++) {
        uint32_t a[4];
        {
            int row = q0 + (lane & 15);
            int g = 2 * ks + (lane >> 4);
            ldsm4(a, sb + row * 64 + ((g ^ ((row >> 1) & 3)) << 4));
        }
        #pragma unroll
        for (int np = 0; np < 4; np++) {
            uint32_t kb[4];
            int tok = 16 * np + (((lane >> 4) & 1) << 3) + (lane & 7);
            int g = 2 * ks + ((lane >> 3) & 1);
            ldsm4(kb, sb + 4096 + tok * 64 + ((g ^ ((tok >> 1) & 3)) << 4));
            mma16816(c[2 * np],     a, kb);
            mma16816(c[2 * np + 1], a, kb + 2);
        }
    }

    // ---- softmax (rows l>>2 and l>>2+8; quad shuffles) ----
    const float scale = 0.17677669529663688f;   // 32^-0.5
    float mLo = -1e30f, mHi = -1e30f;
    #pragma unroll
    for (int t = 0; t < 8; t++) {
        mLo = fmaxf(mLo, fmaxf(c[t][0], c[t][1]));
        mHi = fmaxf(mHi, fmaxf(c[t][2], c[t][3]));
    }
    #pragma unroll
    for (int off = 1; off <= 2; off <<= 1) {
        mLo = fmaxf(mLo, __shfl_xor_sync(0xffffffffu, mLo, off));
        mHi = fmaxf(mHi, __shfl_xor_sync(0xffffffffu, mHi, off));
    }
    float sLo = 0.f, sHi = 0.f;
    #pragma unroll
    for (int t = 0; t < 8; t++) {
        c[t][0] = __expf((c[t][0] - mLo) * scale);
        c[t][1] = __expf((c[t][1] - mLo) * scale);
        c[t][2] = __expf((c[t][2] - mHi) * scale);
        c[t][3] = __expf((c[t][3] - mHi) * scale);
        sLo += c[t][0] + c[t][1];
        sHi += c[t][2] + c[t][3];
    }
    #pragma unroll
    for (int off = 1; off <= 2; off <<= 1) {
        sLo += __shfl_xor_sync(0xffffffffu, sLo, off);
        sHi += __shfl_xor_sync(0xffffffffu, sHi, off);
    }
    float iLo = 1.f / sLo, iHi = 1.f / sHi;

    // ---- P (fp16 A-fragments) ----
    uint32_t pa[4][4];
    #pragma unroll
    for (int kt = 0; kt < 4; kt++) {
        __half2 h0 = __floats2half2_rn(c[2*kt][0] * iLo, c[2*kt][1] * iLo);
        __half2 h1 = __floats2half2_rn(c[2*kt][2] * iHi, c[2*kt][3] * iHi);
        __half2 h2 = __floats2half2_rn(c[2*kt+1][0] * iLo, c[2*kt+1][1] * iLo);
        __half2 h3 = __floats2half2_rn(c[2*kt+1][2] * iHi, c[2*kt+1][3] * iHi);
        pa[kt][0] = *(uint32_t*)&h0;
        pa[kt][1] = *(uint32_t*)&h1;
        pa[kt][2] = *(uint32_t*)&h2;
        pa[kt][3] = *(uint32_t*)&h3;
    }

    // ---- O = P V  (16 x 32), fp32 accum ----
    float o[4][4];
    #pragma unroll
    for (int nt = 0; nt < 4; nt++)
        #pragma unroll
        for (int j = 0; j < 4; j++) o[nt][j] = 0.f;

    #pragma unroll
    for (int kt = 0; kt < 4; kt++) {
        uint32_t vb[4][2];
        #pragma unroll
        for (int pr = 0; pr < 2; pr++) {
            int tok = kt * 16 + (lane & 7) + (((lane >> 3) & 1) << 3);
            int g = pr * 2 + (lane >> 4);
            uint32_t t4[4];
            ldsm4t(t4, sb + 8192 + tok * 64 + ((g ^ ((tok >> 1) & 3)) << 4));
            vb[2*pr][0] = t4[0]; vb[2*pr][1] = t4[1];
            vb[2*pr+1][0] = t4[2]; vb[2*pr+1][1] = t4[3];
        }
        #pragma unroll
        for (int nt = 0; nt < 4; nt++)
            mma16816(o[nt], pa[kt], vb[nt]);
    }

    // ---- write O (fp16) ----
    #pragma unroll
    for (int half = 0; half < 2; half++) {
        int p = q0 + (lane >> 2) + half * 8;
        int tg = b * (HH * WW) + (wi * 8 + (p >> 3)) * WW + wj * 8 + (p & 7);
        __half* op = out + (size_t)tg * CC + head * HD;
        #pragma unroll
        for (int nt = 0; nt < 4; nt++) {
            __half2 hv = __floats2half2_rn(o[nt][half * 2], o[nt][half * 2 + 1]);
            *(__half2*)(op + nt * 8 + 2 * (lane & 3)) = hv;
        }
    }
}

// ---------------- launch -----------------------------------------------------
extern "C" void kernel_launch(void* const* d_in, const int* in_sizes, int n_in,
                              void* d_out, int out_size) {
    const float* x      = (const float*)d_in[0];
    const float* ln1_g  = (const float*)d_in[1];
    const float* ln1_b  = (const float*)d_in[2];
    const float* w_qkv  = (const float*)d_in[3];
    const float* b_qkv  = (const float*)d_in[4];
    const float* w_proj = (const float*)d_in[5];
    const float* b_proj = (const float*)d_in[6];
    const float* ln2_g  = (const float*)d_in[7];
    const float* ln2_b  = (const float*)d_in[8];
    const float* w1     = (const float*)d_in[9];
    const float* b1     = (const float*)d_in[10];
    const float* w2     = (const float*)d_in[11];
    const float* b2     = (const float*)d_in[12];
    float* out = (float*)d_out;

    __half *n1h, *qkvh, *atth, *acth, *wqkvh, *wprojh, *w1h, *w2h;
    float* msa;
    cudaGetSymbolAddress((void**)&n1h,   g_n1h);
    cudaGetSymbolAddress((void**)&qkvh,  g_qkvh);
    cudaGetSymbolAddress((void**)&atth,  g_atth);
    cudaGetSymbolAddress((void**)&acth,  g_acth);
    cudaGetSymbolAddress((void**)&msa,   g_msa);
    cudaGetSymbolAddress((void**)&wqkvh, g_wqkvh);
    cudaGetSymbolAddress((void**)&wprojh,g_wprojh);
    cudaGetSymbolAddress((void**)&w1h,   g_w1h);
    cudaGetSymbolAddress((void**)&w2h,   g_w2h);

    cudaFuncSetAttribute(gemm_h<0,true >, cudaFuncAttributeMaxDynamicSharedMemorySize, SMEM_TOTAL);
    cudaFuncSetAttribute(gemm_h<1,false>, cudaFuncAttributeMaxDynamicSharedMemorySize, SMEM_TOTAL);
    cudaFuncSetAttribute(gemm_h<2,true >, cudaFuncAttributeMaxDynamicSharedMemorySize, SMEM_TOTAL);

    // 0) all weights -> fp16 in one launch
    f2h_all<<<W3E / 256, 256>>>(w_qkv, wqkvh, w_proj, wprojh, w1, w1h, w2, w2h);

    // 1) LN1 (shift dropped: SHIFT==WS so rolls cancel with window partition)
    ln_kernel<<<NTOK, 256>>>(x, ln1_g, ln1_b, n1h);
    // 2) qkv = n1 @ w_qkv + b_qkv           [32768 x 1536] fp16 out
    gemm_h<0,true><<<dim3(1536 / 256, NTOK / 128), 512, SMEM_TOTAL>>>(n1h, wqkvh, b_qkv, nullptr, qkvh, CC, 3 * CC);
    // 3) tensor-core window attention (512 windows x 16 heads)
    attn_mma<<<512 * NHEADS, 128>>>(qkvh, atth);
    // 4) msa = att @ w_proj + b_proj + x    [32768 x 512] fp32 out
    gemm_h<1,false><<<dim3(CC / 256, NTOK / 128), 512, SMEM_TOTAL>>>(atth, wprojh, b_proj, x, msa, CC, CC);
    // 5) LN2
    ln_kernel<<<NTOK, 256>>>(msa, ln2_g, ln2_b, n1h);
    // 6) act = gelu(n1 @ w1 + b1)           [32768 x 2048] fp16 out
    gemm_h<2,true><<<dim3(E4D / 256, NTOK / 128), 512, SMEM_TOTAL>>>(n1h, w1h, b1, nullptr, acth, CC, E4D);
    // 7) out = act @ w2 + b2 + msa          [32768 x 512] fp32 out
    gemm_h<1,false><<<dim3(CC / 256, NTOK / 128), 512, SMEM_TOTAL>>>(acth, w2h, b2, msa, out, E4D, CC);
}